// round 9
// baseline (speedup 1.0000x reference)
#include <cuda_runtime.h>
#include <math.h>

#define NFFT 512
#define HOP  128
#define LSIG 160000
#define BB   16
#define CC   4
#define TT   1251
#define FDIM 257
#define KFEAT (4 * CC * FDIM)   // 4112
#define CF   (CC * FDIM)        // 1028

#define PI_D 3.14159265358979323846
#define SVCOEF ((float)(-2.0 * PI_D * 16000.0 / (512.0 * 340.4)))

struct c2 { float x, y; };

__device__ __forceinline__ c2 cmul(c2 a, c2 b){ c2 r; r.x = a.x*b.x - a.y*b.y; r.y = a.x*b.y + a.y*b.x; return r; }
__device__ __forceinline__ c2 cadd(c2 a, c2 b){ c2 r; r.x = a.x+b.x; r.y = a.y+b.y; return r; }
__device__ __forceinline__ c2 csub(c2 a, c2 b){ c2 r; r.x = a.x-b.x; r.y = a.y-b.y; return r; }
__device__ __forceinline__ c2 mulnegi(c2 a){ c2 r; r.x = a.y; r.y = -a.x; return r; }

// radix-8 DFT: o[k] = sum_j v[j] * w8^{j*k}, w8 = exp(-2*pi*i/8)
__device__ __forceinline__ void radix8(const c2* v, c2* o) {
    const float S = 0.70710678118654752f;
    c2 a0=cadd(v[0],v[4]), a1=csub(v[0],v[4]);
    c2 a2=cadd(v[2],v[6]), a3=csub(v[2],v[6]);
    c2 b0=cadd(v[1],v[5]), b1=csub(v[1],v[5]);
    c2 b2=cadd(v[3],v[7]), b3=csub(v[3],v[7]);
    c2 ia3 = mulnegi(a3), ib3 = mulnegi(b3);
    c2 c0=cadd(a0,a2), c1=csub(a0,a2);
    c2 e2=cadd(a1,ia3), e3=csub(a1,ia3);
    c2 d0=cadd(b0,b2), d1=csub(b0,b2);
    c2 d2=cadd(b1,ib3), d3=csub(b1,ib3);
    c2 w1d2; w1d2.x = S*(d2.x + d2.y); w1d2.y = S*(d2.y - d2.x);
    c2 w3d3; w3d3.x = S*(d3.y - d3.x); w3d3.y = -S*(d3.x + d3.y);
    c2 id1 = mulnegi(d1);
    o[0]=cadd(c0,d0);    o[4]=csub(c0,d0);
    o[2]=cadd(c1,id1);   o[6]=csub(c1,id1);
    o[1]=cadd(e2,w1d2);  o[5]=csub(e2,w1d2);
    o[3]=cadd(e3,w3d3);  o[7]=csub(e3,w3d3);
}

__device__ float g_dt[CC];   // tdoa[c] - tdoa[0]

// ---------------------------------------------------------------------------
// Prep: TDOA only (64 threads, one accurate trig pair each, smem reduce)
// ---------------------------------------------------------------------------
__global__ void prep_kernel(const float* __restrict__ angle,
                            const float* __restrict__ mic_pos) {
    __shared__ float d2[BB * CC];
    const int tid = threadIdx.x;           // 64 threads: tid = b*CC + c
    const int b = tid >> 2;
    const float half_pi = (float)(PI_D / 2.0);
    float sin90 = sinf(half_pi);           // fp32 quirks reproduced
    float cos90 = cosf(half_pi);
    float rad = -angle[b] * (float)(PI_D / 180.0);
    float lx = cosf(rad) * sin90;
    float ly = sinf(rad) * sin90;
    float lz = cos90;                      // DIST = 1.0
    const float* mp = mic_pos + tid * 3;
    float dx = mp[0] - lx, dy = mp[1] - ly, dz = mp[2] - lz;
    d2[tid] = dx * dx + dy * dy + dz * dz;
    __syncthreads();
    if (tid < CC) {
        float s = 0.f;
        for (int bb = 0; bb < BB; bb++) s += d2[bb * CC + tid];
        d2[tid] = sqrtf(s);                // reuse as tdoa[c]
    }
    __syncthreads();
    if (tid < CC) g_dt[tid] = d2[tid] - d2[0];
}

// ---------------------------------------------------------------------------
// STFT: 256-thr block = 4 FFT units (64 thr). One packed complex FFT (two
// real channels, one frame) per unit via 3 radix-8 register passes.
// smem: single buffer reused (skewed exchange, then natural-order result) —
// the nat data is only written after ALL sd reads complete (barrier between).
// ---------------------------------------------------------------------------
__global__ void __launch_bounds__(256, 7) stft_kernel(const float* __restrict__ x,
                                                      float* __restrict__ out) {
    __shared__ c2 sd[4][520];     // skewed 8x65 for p1->p2; reused as nat[512]

    const int tid = threadIdx.x;
    const int u   = tid >> 6;        // FFT unit 0..3
    const int tau = tid & 63;
    const int t   = blockIdx.x * 4 + u;
    const int by  = blockIdx.y;
    const int b   = by >> 1;
    const int pr  = by & 1;          // channel pair (2pr, 2pr+1)
    const bool active = (t < TT);

    c2 v[8], o8[8];

    // ---- pass 1: windowed load, radix-8 over n2, twiddle W64^{n1*k0} ----
    if (active) {
        const float S = 0.70710678118654752f;
        const float c8[8] = {1.f,  S, 0.f, -S, -1.f, -S,  0.f,  S};
        const float s8[8] = {0.f,  S, 1.f,  S,  0.f, -S, -1.f, -S};
        float sth, cth;
        __sincosf((float)(2.0 * PI_D / 512.0) * (float)tau, &sth, &cth);

        const float* xa = x + (size_t)(b * CC + 2 * pr) * LSIG;
        const float* xb = xa + LSIG;
        const int p0 = t * HOP - 256;
        if (t >= 2 && t <= 1248) {           // interior: no reflection possible
#pragma unroll
            for (int n2 = 0; n2 < 8; n2++) {
                int s = p0 + n2 * 64 + tau;
                float cosn = c8[n2] * cth - s8[n2] * sth;
                float w = 0.5f - 0.5f * cosn;            // Hann
                v[n2].x = xa[s] * w;
                v[n2].y = xb[s] * w;
            }
        } else {
#pragma unroll
            for (int n2 = 0; n2 < 8; n2++) {
                int p = p0 + n2 * 64 + tau;
                int s = (p < 0) ? -p : ((p >= LSIG) ? 2 * LSIG - 2 - p : p);
                float cosn = c8[n2] * cth - s8[n2] * sth;
                float w = 0.5f - 0.5f * cosn;
                v[n2].x = xa[s] * w;
                v[n2].y = xb[s] * w;
            }
        }
        radix8(v, o8);
        int n1 = tau >> 3;
        float ss, cs;
        __sincosf((float)(-2.0 * PI_D / 64.0) * (float)n1, &ss, &cs);
        c2 step; step.x = cs; step.y = ss;                   // W64^{n1}
        c2 w; w.x = 1.f; w.y = 0.f;
#pragma unroll
        for (int k0 = 0; k0 < 8; k0++) {
            sd[u][k0 * 65 + tau] = cmul(o8[k0], w);          // * W64^{n1*k0}
            w = cmul(w, step);
        }
    }
    __syncthreads();

    // ---- pass 2 + 3 fused: radix-8 over n1, twiddle, SHFL transpose,
    //      radix-8 over n0 ----
    if (active) {
        const int k0 = tau >> 3;
        const int l  = tau & 7;      // = n0 in pass 2, = k1 in pass 3
#pragma unroll
        for (int n1 = 0; n1 < 8; n1++) v[n1] = sd[u][k0 * 65 + n1 * 8 + l];
        radix8(v, o8);
        {   // twiddle W512^{n0*k0} * W64^{n0*k1},  n0 = l
            float s0, c0, ss, cs;
            __sincosf((float)(-2.0 * PI_D / 512.0) * (float)(l * k0), &s0, &c0);
            __sincosf((float)(-2.0 * PI_D / 64.0) * (float)l, &ss, &cs);
            c2 w;    w.x = c0;   w.y = s0;
            c2 step; step.x = cs; step.y = ss;
#pragma unroll
            for (int k1 = 0; k1 < 8; k1++) {
                o8[k1] = cmul(o8[k1], w);
                w = cmul(w, step);
            }
        }
        // 8x8 XOR-transpose within the 8-lane group (same k0):
#pragma unroll
        for (int s = 1; s < 8; s <<= 1) {
#pragma unroll
            for (int j0 = 0; j0 < 8; j0++) {
                if (j0 & s) continue;
                const int j1 = j0 | s;
                c2 a = (l & s) ? o8[j0] : o8[j1];
                c2 bq;
                bq.x = __shfl_xor_sync(0xFFFFFFFFu, a.x, s);
                bq.y = __shfl_xor_sync(0xFFFFFFFFu, a.y, s);
                if (l & s) o8[j0] = bq; else o8[j1] = bq;
            }
        }
        // pass 3: radix-8 over n0; results X[64*k2 + 8*l + k0] in v[k2]
        radix8(o8, v);
    }
    __syncthreads();   // ALL sd reads done -> safe to reuse the buffer as nat

    // ---- store natural order into the SAME buffer ----
    c2* nat = sd[u];
    if (active) {
        const int k0 = tau >> 3, l = tau & 7;
#pragma unroll
        for (int k2 = 0; k2 < 8; k2++) nat[k2 * 64 + l * 8 + k0] = v[k2];
    }
    __syncthreads();

    // ---- unpack 2 real spectra + write X groups + computed SV groups ----
    if (active) {
        float* row = out + ((size_t)b * TT + t) * KFEAT;
        const int ca = 2 * pr, cb = 2 * pr + 1;
        const float dta = g_dt[ca];
        const float dtb = g_dt[cb];
        float* aBase = row + ca * FDIM;
        float* bBase = row + cb * FDIM;
        // incremental steering-vector rotation: sv(k+64) = sv(k)*rot
        c2 sva, svb, rota, rotb;
        __sincosf(SVCOEF * (float)tau * dta, &sva.y, &sva.x);
        __sincosf(SVCOEF * (float)tau * dtb, &svb.y, &svb.x);
        __sincosf(SVCOEF * 64.f * dta, &rota.y, &rota.x);
        __sincosf(SVCOEF * 64.f * dtb, &rotb.y, &rotb.x);
        for (int k = tau; k <= 256; k += 64) {
            c2 zk = nat[k];
            c2 zm = nat[(512 - k) & 511];
            aBase[k]          = 0.5f * (zk.x + zm.x);   // A.re
            aBase[CF + k]     = 0.5f * (zk.y - zm.y);   // A.im
            bBase[k]          = 0.5f * (zk.y + zm.y);   // B.re
            bBase[CF + k]     = 0.5f * (zm.x - zk.x);   // B.im
            aBase[2 * CF + k] = 0.5f * sva.x;           // sv.re / ||sv||
            aBase[3 * CF + k] = 0.5f * sva.y;           // sv.im
            bBase[2 * CF + k] = 0.5f * svb.x;
            bBase[3 * CF + k] = 0.5f * svb.y;
            sva = cmul(sva, rota);
            svb = cmul(svb, rotb);
        }
    }
}

// ---------------------------------------------------------------------------
extern "C" void kernel_launch(void* const* d_in, const int* in_sizes, int n_in,
                              void* d_out, int out_size) {
    const float* x     = (const float*)d_in[0];
    const float* angle = (const float*)d_in[1];
    const float* mic   = (const float*)d_in[2];
    float* out = (float*)d_out;

    prep_kernel<<<1, 64>>>(angle, mic);

    dim3 grid((TT + 3) / 4, BB * 2);
    stft_kernel<<<grid, 256>>>(x, out);
}

// round 10
// speedup vs baseline: 1.2484x; 1.2484x over previous
#include <cuda_runtime.h>
#include <math.h>

#define NFFT 512
#define HOP  128
#define LSIG 160000
#define BB   16
#define CC   4
#define TT   1251
#define FDIM 257
#define KFEAT (4 * CC * FDIM)   // 4112
#define CF   (CC * FDIM)        // 1028

#define PI_D 3.14159265358979323846
#define SVCOEF ((float)(-2.0 * PI_D * 16000.0 / (512.0 * 340.4)))

struct c2 { float x, y; };

__device__ __forceinline__ c2 cmul(c2 a, c2 b){ c2 r; r.x = a.x*b.x - a.y*b.y; r.y = a.x*b.y + a.y*b.x; return r; }
__device__ __forceinline__ c2 cadd(c2 a, c2 b){ c2 r; r.x = a.x+b.x; r.y = a.y+b.y; return r; }
__device__ __forceinline__ c2 csub(c2 a, c2 b){ c2 r; r.x = a.x-b.x; r.y = a.y-b.y; return r; }
__device__ __forceinline__ c2 mulnegi(c2 a){ c2 r; r.x = a.y; r.y = -a.x; return r; }

// radix-8 DFT: o[k] = sum_j v[j] * w8^{j*k}, w8 = exp(-2*pi*i/8)
__device__ __forceinline__ void radix8(const c2* v, c2* o) {
    const float S = 0.70710678118654752f;
    c2 a0=cadd(v[0],v[4]), a1=csub(v[0],v[4]);
    c2 a2=cadd(v[2],v[6]), a3=csub(v[2],v[6]);
    c2 b0=cadd(v[1],v[5]), b1=csub(v[1],v[5]);
    c2 b2=cadd(v[3],v[7]), b3=csub(v[3],v[7]);
    c2 ia3 = mulnegi(a3), ib3 = mulnegi(b3);
    c2 c0=cadd(a0,a2), c1=csub(a0,a2);
    c2 e2=cadd(a1,ia3), e3=csub(a1,ia3);
    c2 d0=cadd(b0,b2), d1=csub(b0,b2);
    c2 d2=cadd(b1,ib3), d3=csub(b1,ib3);
    c2 w1d2; w1d2.x = S*(d2.x + d2.y); w1d2.y = S*(d2.y - d2.x);
    c2 w3d3; w3d3.x = S*(d3.y - d3.x); w3d3.y = -S*(d3.x + d3.y);
    c2 id1 = mulnegi(d1);
    o[0]=cadd(c0,d0);    o[4]=csub(c0,d0);
    o[2]=cadd(c1,id1);   o[6]=csub(c1,id1);
    o[1]=cadd(e2,w1d2);  o[5]=csub(e2,w1d2);
    o[3]=cadd(e3,w3d3);  o[7]=csub(e3,w3d3);
}

__device__ float g_dt[CC];   // tdoa[c] - tdoa[0]

// ---------------------------------------------------------------------------
// Prep: TDOA only (64 threads, one accurate trig pair each, smem reduce)
// ---------------------------------------------------------------------------
__global__ void prep_kernel(const float* __restrict__ angle,
                            const float* __restrict__ mic_pos) {
    __shared__ float d2[BB * CC];
    const int tid = threadIdx.x;           // 64 threads: tid = b*CC + c
    const int b = tid >> 2;
    const float half_pi = (float)(PI_D / 2.0);
    float sin90 = sinf(half_pi);           // fp32 quirks reproduced
    float cos90 = cosf(half_pi);
    float rad = -angle[b] * (float)(PI_D / 180.0);
    float lx = cosf(rad) * sin90;
    float ly = sinf(rad) * sin90;
    float lz = cos90;                      // DIST = 1.0
    const float* mp = mic_pos + tid * 3;
    float dx = mp[0] - lx, dy = mp[1] - ly, dz = mp[2] - lz;
    d2[tid] = dx * dx + dy * dy + dz * dz;
    __syncthreads();
    if (tid < CC) {
        float s = 0.f;
        for (int bb = 0; bb < BB; bb++) s += d2[bb * CC + tid];
        d2[tid] = sqrtf(s);                // reuse as tdoa[c]
    }
    __syncthreads();
    if (tid < CC) g_dt[tid] = d2[tid] - d2[0];
}

// ---------------------------------------------------------------------------
// STFT: 256-thr block = 4 FFT units (64 thr). One packed complex FFT (two
// real channels, one frame) per unit via 3 radix-8 register passes.
// Twiddles in registers; pass2->pass3 exchange via in-register 8x8 XOR
// transpose (shfl). Epilogue recomputes the steering vector with __sincosf
// (no table loads) and writes all 4 feature groups coalesced.
// ---------------------------------------------------------------------------
__global__ void __launch_bounds__(256) stft_kernel(const float* __restrict__ x,
                                                   float* __restrict__ out) {
    __shared__ c2 sd[4][520];     // skewed: 8 rows of 65 (pass1 -> pass2 only)
    __shared__ c2 nat[4][512];    // natural-order result

    const int tid = threadIdx.x;
    const int u   = tid >> 6;        // FFT unit 0..3
    const int tau = tid & 63;
    const int t   = blockIdx.x * 4 + u;
    const int by  = blockIdx.y;
    const int b   = by >> 1;
    const int pr  = by & 1;          // channel pair (2pr, 2pr+1)
    const bool active = (t < TT);

    c2 v[8], o8[8];

    // ---- pass 1: windowed load, radix-8 over n2, twiddle W64^{n1*k0} ----
    if (active) {
        const float S = 0.70710678118654752f;
        const float c8[8] = {1.f,  S, 0.f, -S, -1.f, -S,  0.f,  S};
        const float s8[8] = {0.f,  S, 1.f,  S,  0.f, -S, -1.f, -S};
        float sth, cth;
        __sincosf((float)(2.0 * PI_D / 512.0) * (float)tau, &sth, &cth);

        const float* xa = x + (size_t)(b * CC + 2 * pr) * LSIG;
        const float* xb = xa + LSIG;
        const int p0 = t * HOP - 256;
        if (t >= 2 && t <= 1248) {           // interior: no reflection possible
#pragma unroll
            for (int n2 = 0; n2 < 8; n2++) {
                int s = p0 + n2 * 64 + tau;
                float cosn = c8[n2] * cth - s8[n2] * sth;    // cos(2*pi*n/512)
                float w = 0.5f - 0.5f * cosn;                // Hann
                v[n2].x = xa[s] * w;
                v[n2].y = xb[s] * w;
            }
        } else {
#pragma unroll
            for (int n2 = 0; n2 < 8; n2++) {
                int p = p0 + n2 * 64 + tau;
                int s = (p < 0) ? -p : ((p >= LSIG) ? 2 * LSIG - 2 - p : p);
                float cosn = c8[n2] * cth - s8[n2] * sth;
                float w = 0.5f - 0.5f * cosn;
                v[n2].x = xa[s] * w;
                v[n2].y = xb[s] * w;
            }
        }
        radix8(v, o8);
        int n1 = tau >> 3;
        float ss, cs;
        __sincosf((float)(-2.0 * PI_D / 64.0) * (float)n1, &ss, &cs);
        c2 step; step.x = cs; step.y = ss;                   // W64^{n1}
        c2 w; w.x = 1.f; w.y = 0.f;
#pragma unroll
        for (int k0 = 0; k0 < 8; k0++) {
            sd[u][k0 * 65 + tau] = cmul(o8[k0], w);          // * W64^{n1*k0}
            w = cmul(w, step);
        }
    }
    __syncthreads();

    // ---- pass 2 + 3 fused: radix-8 over n1, twiddle, SHFL transpose,
    //      radix-8 over n0, store natural order ----
    if (active) {
        const int k0 = tau >> 3;
        const int l  = tau & 7;      // = n0 in pass 2, = k1 in pass 3
#pragma unroll
        for (int n1 = 0; n1 < 8; n1++) v[n1] = sd[u][k0 * 65 + n1 * 8 + l];
        radix8(v, o8);
        {   // twiddle W512^{n0*k0} * W64^{n0*k1},  n0 = l
            float s0, c0, ss, cs;
            __sincosf((float)(-2.0 * PI_D / 512.0) * (float)(l * k0), &s0, &c0);
            __sincosf((float)(-2.0 * PI_D / 64.0) * (float)l, &ss, &cs);
            c2 w;    w.x = c0;   w.y = s0;
            c2 step; step.x = cs; step.y = ss;
#pragma unroll
            for (int k1 = 0; k1 < 8; k1++) {
                o8[k1] = cmul(o8[k1], w);
                w = cmul(w, step);
            }
        }
        // 8x8 XOR-transpose within the 8-lane group (same k0):
        // before: lane l = n0 holds o8[k1];  after: lane l = k1 holds o8[n0]
#pragma unroll
        for (int s = 1; s < 8; s <<= 1) {
#pragma unroll
            for (int j0 = 0; j0 < 8; j0++) {
                if (j0 & s) continue;
                const int j1 = j0 | s;
                c2 a = (l & s) ? o8[j0] : o8[j1];
                c2 bq;
                bq.x = __shfl_xor_sync(0xFFFFFFFFu, a.x, s);
                bq.y = __shfl_xor_sync(0xFFFFFFFFu, a.y, s);
                if (l & s) o8[j0] = bq; else o8[j1] = bq;
            }
        }
        // pass 3: radix-8 over n0; output X[64*k2 + 8*k1 + k0], k1 = l
        radix8(o8, v);
#pragma unroll
        for (int k2 = 0; k2 < 8; k2++) nat[u][k2 * 64 + l * 8 + k0] = v[k2];
    }
    __syncthreads();

    // ---- unpack 2 real spectra + write X groups + computed SV groups ----
    if (active) {
        float* row = out + ((size_t)b * TT + t) * KFEAT;
        const int ca = 2 * pr, cb = 2 * pr + 1;
        const float dta = g_dt[ca];
        const float dtb = g_dt[cb];
        float* aBase = row + ca * FDIM;
        float* bBase = row + cb * FDIM;
        for (int k = tau; k <= 256; k += 64) {
            c2 zk = nat[u][k];
            c2 zm = nat[u][(512 - k) & 511];
            aBase[k]          = 0.5f * (zk.x + zm.x);   // A.re
            aBase[CF + k]     = 0.5f * (zk.y - zm.y);   // A.im
            bBase[k]          = 0.5f * (zk.y + zm.y);   // B.re
            bBase[CF + k]     = 0.5f * (zm.x - zk.x);   // B.im
            float sa, cA, sb, cB;
            __sincosf(SVCOEF * (float)k * dta, &sa, &cA);
            __sincosf(SVCOEF * (float)k * dtb, &sb, &cB);
            aBase[2 * CF + k] = 0.5f * cA;              // sv.re / ||sv||
            aBase[3 * CF + k] = 0.5f * sa;              // sv.im
            bBase[2 * CF + k] = 0.5f * cB;
            bBase[3 * CF + k] = 0.5f * sb;
        }
    }
}

// ---------------------------------------------------------------------------
extern "C" void kernel_launch(void* const* d_in, const int* in_sizes, int n_in,
                              void* d_out, int out_size) {
    const float* x     = (const float*)d_in[0];
    const float* angle = (const float*)d_in[1];
    const float* mic   = (const float*)d_in[2];
    float* out = (float*)d_out;

    prep_kernel<<<1, 64>>>(angle, mic);

    dim3 grid((TT + 3) / 4, BB * 2);
    stft_kernel<<<grid, 256>>>(x, out);
}

// round 11
// speedup vs baseline: 1.2577x; 1.0074x over previous
#include <cuda_runtime.h>
#include <math.h>

#define NFFT 512
#define HOP  128
#define LSIG 160000
#define BB   16
#define CC   4
#define TT   1251
#define FDIM 257
#define KFEAT (4 * CC * FDIM)   // 4112
#define CF   (CC * FDIM)        // 1028

#define PI_D 3.14159265358979323846
#define SVCOEF ((float)(-2.0 * PI_D * 16000.0 / (512.0 * 340.4)))

// sd skew stride: 72 = 8 (mod 16) -> pass-2 LDS.64 reads conflict-free
#define SDS 72
// diagonal skew for the natural-order planes (4B elements, conflict-free writes)
#define NSK(a) ((a) + 4 * ((a) >> 5))

struct c2 { float x, y; };

__device__ __forceinline__ c2 cmul(c2 a, c2 b){ c2 r; r.x = a.x*b.x - a.y*b.y; r.y = a.x*b.y + a.y*b.x; return r; }
__device__ __forceinline__ c2 cadd(c2 a, c2 b){ c2 r; r.x = a.x+b.x; r.y = a.y+b.y; return r; }
__device__ __forceinline__ c2 csub(c2 a, c2 b){ c2 r; r.x = a.x-b.x; r.y = a.y-b.y; return r; }
__device__ __forceinline__ c2 mulnegi(c2 a){ c2 r; r.x = a.y; r.y = -a.x; return r; }

// radix-8 DFT: o[k] = sum_j v[j] * w8^{j*k}, w8 = exp(-2*pi*i/8)
__device__ __forceinline__ void radix8(const c2* v, c2* o) {
    const float S = 0.70710678118654752f;
    c2 a0=cadd(v[0],v[4]), a1=csub(v[0],v[4]);
    c2 a2=cadd(v[2],v[6]), a3=csub(v[2],v[6]);
    c2 b0=cadd(v[1],v[5]), b1=csub(v[1],v[5]);
    c2 b2=cadd(v[3],v[7]), b3=csub(v[3],v[7]);
    c2 ia3 = mulnegi(a3), ib3 = mulnegi(b3);
    c2 c0=cadd(a0,a2), c1=csub(a0,a2);
    c2 e2=cadd(a1,ia3), e3=csub(a1,ia3);
    c2 d0=cadd(b0,b2), d1=csub(b0,b2);
    c2 d2=cadd(b1,ib3), d3=csub(b1,ib3);
    c2 w1d2; w1d2.x = S*(d2.x + d2.y); w1d2.y = S*(d2.y - d2.x);
    c2 w3d3; w3d3.x = S*(d3.y - d3.x); w3d3.y = -S*(d3.x + d3.y);
    c2 id1 = mulnegi(d1);
    o[0]=cadd(c0,d0);    o[4]=csub(c0,d0);
    o[2]=cadd(c1,id1);   o[6]=csub(c1,id1);
    o[1]=cadd(e2,w1d2);  o[5]=csub(e2,w1d2);
    o[3]=cadd(e3,w3d3);  o[7]=csub(e3,w3d3);
}

__device__ float g_dt[CC];   // tdoa[c] - tdoa[0]

// ---------------------------------------------------------------------------
// Prep: TDOA only (64 threads, one accurate trig pair each, smem reduce)
// ---------------------------------------------------------------------------
__global__ void prep_kernel(const float* __restrict__ angle,
                            const float* __restrict__ mic_pos) {
    __shared__ float d2[BB * CC];
    const int tid = threadIdx.x;           // 64 threads: tid = b*CC + c
    const int b = tid >> 2;
    const float half_pi = (float)(PI_D / 2.0);
    float sin90 = sinf(half_pi);           // fp32 quirks reproduced
    float cos90 = cosf(half_pi);
    float rad = -angle[b] * (float)(PI_D / 180.0);
    float lx = cosf(rad) * sin90;
    float ly = sinf(rad) * sin90;
    float lz = cos90;                      // DIST = 1.0
    const float* mp = mic_pos + tid * 3;
    float dx = mp[0] - lx, dy = mp[1] - ly, dz = mp[2] - lz;
    d2[tid] = dx * dx + dy * dy + dz * dz;
    __syncthreads();
    if (tid < CC) {
        float s = 0.f;
        for (int bb = 0; bb < BB; bb++) s += d2[bb * CC + tid];
        d2[tid] = sqrtf(s);                // reuse as tdoa[c]
    }
    __syncthreads();
    if (tid < CC) g_dt[tid] = d2[tid] - d2[0];
}

// ---------------------------------------------------------------------------
// STFT: 256-thr block = 4 FFT units (64 thr). One packed complex FFT (two
// real channels, one frame) per unit via 3 radix-8 register passes.
// Bank-conflict-free shared exchanges: sd skew 72 (pass1->pass2), diagonal-
// skewed re/im planes for the natural-order result.
// ---------------------------------------------------------------------------
__global__ void __launch_bounds__(256) stft_kernel(const float* __restrict__ x,
                                                   float* __restrict__ out) {
    __shared__ c2 sd[4][568];        // rows of SDS=72, max idx 7*72+63=567
    __shared__ float natR[4][572];   // NSK(511)=571
    __shared__ float natI[4][572];

    const int tid = threadIdx.x;
    const int u   = tid >> 6;        // FFT unit 0..3
    const int tau = tid & 63;
    const int t   = blockIdx.x * 4 + u;
    const int by  = blockIdx.y;
    const int b   = by >> 1;
    const int pr  = by & 1;          // channel pair (2pr, 2pr+1)
    const bool active = (t < TT);

    c2 v[8], o8[8];

    // ---- pass 1: windowed load, radix-8 over n2, twiddle W64^{n1*k0} ----
    if (active) {
        const float S = 0.70710678118654752f;
        const float c8[8] = {1.f,  S, 0.f, -S, -1.f, -S,  0.f,  S};
        const float s8[8] = {0.f,  S, 1.f,  S,  0.f, -S, -1.f, -S};
        float sth, cth;
        __sincosf((float)(2.0 * PI_D / 512.0) * (float)tau, &sth, &cth);

        const float* xa = x + (size_t)(b * CC + 2 * pr) * LSIG;
        const float* xb = xa + LSIG;
        const int p0 = t * HOP - 256;
        if (t >= 2 && t <= 1248) {           // interior: no reflection possible
#pragma unroll
            for (int n2 = 0; n2 < 8; n2++) {
                int s = p0 + n2 * 64 + tau;
                float cosn = c8[n2] * cth - s8[n2] * sth;    // cos(2*pi*n/512)
                float w = 0.5f - 0.5f * cosn;                // Hann
                v[n2].x = xa[s] * w;
                v[n2].y = xb[s] * w;
            }
        } else {
#pragma unroll
            for (int n2 = 0; n2 < 8; n2++) {
                int p = p0 + n2 * 64 + tau;
                int s = (p < 0) ? -p : ((p >= LSIG) ? 2 * LSIG - 2 - p : p);
                float cosn = c8[n2] * cth - s8[n2] * sth;
                float w = 0.5f - 0.5f * cosn;
                v[n2].x = xa[s] * w;
                v[n2].y = xb[s] * w;
            }
        }
        radix8(v, o8);
        int n1 = tau >> 3;
        float ss, cs;
        __sincosf((float)(-2.0 * PI_D / 64.0) * (float)n1, &ss, &cs);
        c2 step; step.x = cs; step.y = ss;                   // W64^{n1}
        c2 w; w.x = 1.f; w.y = 0.f;
#pragma unroll
        for (int k0 = 0; k0 < 8; k0++) {
            sd[u][k0 * SDS + tau] = cmul(o8[k0], w);         // * W64^{n1*k0}
            w = cmul(w, step);
        }
    }
    __syncthreads();

    // ---- pass 2 + 3 fused: radix-8 over n1, twiddle, SHFL transpose,
    //      radix-8 over n0, store natural order (skewed planes) ----
    if (active) {
        const int k0 = tau >> 3;
        const int l  = tau & 7;      // = n0 in pass 2, = k1 in pass 3
#pragma unroll
        for (int n1 = 0; n1 < 8; n1++) v[n1] = sd[u][k0 * SDS + n1 * 8 + l];
        radix8(v, o8);
        {   // twiddle W512^{n0*k0} * W64^{n0*k1},  n0 = l
            float s0, c0, ss, cs;
            __sincosf((float)(-2.0 * PI_D / 512.0) * (float)(l * k0), &s0, &c0);
            __sincosf((float)(-2.0 * PI_D / 64.0) * (float)l, &ss, &cs);
            c2 w;    w.x = c0;   w.y = s0;
            c2 step; step.x = cs; step.y = ss;
#pragma unroll
            for (int k1 = 0; k1 < 8; k1++) {
                o8[k1] = cmul(o8[k1], w);
                w = cmul(w, step);
            }
        }
        // 8x8 XOR-transpose within the 8-lane group (same k0):
        // before: lane l = n0 holds o8[k1];  after: lane l = k1 holds o8[n0]
#pragma unroll
        for (int s = 1; s < 8; s <<= 1) {
#pragma unroll
            for (int j0 = 0; j0 < 8; j0++) {
                if (j0 & s) continue;
                const int j1 = j0 | s;
                c2 a = (l & s) ? o8[j0] : o8[j1];
                c2 bq;
                bq.x = __shfl_xor_sync(0xFFFFFFFFu, a.x, s);
                bq.y = __shfl_xor_sync(0xFFFFFFFFu, a.y, s);
                if (l & s) o8[j0] = bq; else o8[j1] = bq;
            }
        }
        // pass 3: radix-8 over n0; output X[64*k2 + 8*k1 + k0], k1 = l
        radix8(o8, v);
#pragma unroll
        for (int k2 = 0; k2 < 8; k2++) {
            int a  = k2 * 64 + l * 8 + k0;
            int sa = NSK(a);
            natR[u][sa] = v[k2].x;
            natI[u][sa] = v[k2].y;
        }
    }
    __syncthreads();

    // ---- unpack 2 real spectra + write X groups + computed SV groups ----
    if (active) {
        float* row = out + ((size_t)b * TT + t) * KFEAT;
        const int ca = 2 * pr, cb = 2 * pr + 1;
        const float dta = g_dt[ca];
        const float dtb = g_dt[cb];
        float* aBase = row + ca * FDIM;
        float* bBase = row + cb * FDIM;
        for (int k = tau; k <= 256; k += 64) {
            int mk = (512 - k) & 511;
            int ska = NSK(k), skm = NSK(mk);
            c2 zk, zm;
            zk.x = natR[u][ska]; zk.y = natI[u][ska];
            zm.x = natR[u][skm]; zm.y = natI[u][skm];
            aBase[k]          = 0.5f * (zk.x + zm.x);   // A.re
            aBase[CF + k]     = 0.5f * (zk.y - zm.y);   // A.im
            bBase[k]          = 0.5f * (zk.y + zm.y);   // B.re
            bBase[CF + k]     = 0.5f * (zm.x - zk.x);   // B.im
            float sa, cA, sb, cB;
            __sincosf(SVCOEF * (float)k * dta, &sa, &cA);
            __sincosf(SVCOEF * (float)k * dtb, &sb, &cB);
            aBase[2 * CF + k] = 0.5f * cA;              // sv.re / ||sv||
            aBase[3 * CF + k] = 0.5f * sa;              // sv.im
            bBase[2 * CF + k] = 0.5f * cB;
            bBase[3 * CF + k] = 0.5f * sb;
        }
    }
}

// ---------------------------------------------------------------------------
extern "C" void kernel_launch(void* const* d_in, const int* in_sizes, int n_in,
                              void* d_out, int out_size) {
    const float* x     = (const float*)d_in[0];
    const float* angle = (const float*)d_in[1];
    const float* mic   = (const float*)d_in[2];
    float* out = (float*)d_out;

    prep_kernel<<<1, 64>>>(angle, mic);

    dim3 grid((TT + 3) / 4, BB * 2);
    stft_kernel<<<grid, 256>>>(x, out);
}

// round 13
// speedup vs baseline: 1.3143x; 1.0450x over previous
#include <cuda_runtime.h>
#include <math.h>

#define NFFT 512
#define HOP  128
#define LSIG 160000
#define BB   16
#define CC   4
#define TT   1251
#define FDIM 257
#define KFEAT (4 * CC * FDIM)   // 4112
#define CF   (CC * FDIM)        // 1028

#define PI_D 3.14159265358979323846
#define SVCOEF ((float)(-2.0 * PI_D * 16000.0 / (512.0 * 340.4)))

// pass1->pass2 skew stride: 72 = 8 (mod 16) -> conflict-free (proven R11)
#define SDS 72
// pass2->pass3 exchange (split 4B planes): injective, conflict-free both ways
#define EXI(k0, kk, nn) (72 * (k0) + 8 * (kk) + ((nn) ^ (kk)))
// natural-order diagonal skew (proven R11): injective, conflict-free
#define NSK(a) ((a) + 4 * ((a) >> 5))

struct c2 { float x, y; };

__device__ __forceinline__ c2 cmul(c2 a, c2 b){ c2 r; r.x = a.x*b.x - a.y*b.y; r.y = a.x*b.y + a.y*b.x; return r; }
__device__ __forceinline__ c2 cadd(c2 a, c2 b){ c2 r; r.x = a.x+b.x; r.y = a.y+b.y; return r; }
__device__ __forceinline__ c2 csub(c2 a, c2 b){ c2 r; r.x = a.x-b.x; r.y = a.y-b.y; return r; }
__device__ __forceinline__ c2 mulnegi(c2 a){ c2 r; r.x = a.y; r.y = -a.x; return r; }

// radix-8 DFT: o[k] = sum_j v[j] * w8^{j*k}, w8 = exp(-2*pi*i/8)
__device__ __forceinline__ void radix8(const c2* v, c2* o) {
    const float S = 0.70710678118654752f;
    c2 a0=cadd(v[0],v[4]), a1=csub(v[0],v[4]);
    c2 a2=cadd(v[2],v[6]), a3=csub(v[2],v[6]);
    c2 b0=cadd(v[1],v[5]), b1=csub(v[1],v[5]);
    c2 b2=cadd(v[3],v[7]), b3=csub(v[3],v[7]);
    c2 ia3 = mulnegi(a3), ib3 = mulnegi(b3);
    c2 c0=cadd(a0,a2), c1=csub(a0,a2);
    c2 e2=cadd(a1,ia3), e3=csub(a1,ia3);
    c2 d0=cadd(b0,b2), d1=csub(b0,b2);
    c2 d2=cadd(b1,ib3), d3=csub(b1,ib3);
    c2 w1d2; w1d2.x = S*(d2.x + d2.y); w1d2.y = S*(d2.y - d2.x);
    c2 w3d3; w3d3.x = S*(d3.y - d3.x); w3d3.y = -S*(d3.x + d3.y);
    c2 id1 = mulnegi(d1);
    o[0]=cadd(c0,d0);    o[4]=csub(c0,d0);
    o[2]=cadd(c1,id1);   o[6]=csub(c1,id1);
    o[1]=cadd(e2,w1d2);  o[5]=csub(e2,w1d2);
    o[3]=cadd(e3,w3d3);  o[7]=csub(e3,w3d3);
}

__device__ float g_dt[CC];   // tdoa[c] - tdoa[0]

// ---------------------------------------------------------------------------
// Prep: TDOA only (64 threads, one accurate trig pair each, smem reduce)
// ---------------------------------------------------------------------------
__global__ void prep_kernel(const float* __restrict__ angle,
                            const float* __restrict__ mic_pos) {
    __shared__ float d2[BB * CC];
    const int tid = threadIdx.x;           // 64 threads: tid = b*CC + c
    const int b = tid >> 2;
    const float half_pi = (float)(PI_D / 2.0);
    float sin90 = sinf(half_pi);           // fp32 quirks reproduced
    float cos90 = cosf(half_pi);
    float rad = -angle[b] * (float)(PI_D / 180.0);
    float lx = cosf(rad) * sin90;
    float ly = sinf(rad) * sin90;
    float lz = cos90;                      // DIST = 1.0
    const float* mp = mic_pos + tid * 3;
    float dx = mp[0] - lx, dy = mp[1] - ly, dz = mp[2] - lz;
    d2[tid] = dx * dx + dy * dy + dz * dz;
    __syncthreads();
    if (tid < CC) {
        float s = 0.f;
        for (int bb = 0; bb < BB; bb++) s += d2[bb * CC + tid];
        d2[tid] = sqrtf(s);                // reuse as tdoa[c]
    }
    __syncthreads();
    if (tid < CC) g_dt[tid] = d2[tid] - d2[0];
}

// ---------------------------------------------------------------------------
// STFT: 256-thr block = 4 FFT units (64 thr). One packed complex FFT (two
// real channels, one frame) per unit via 3 radix-8 register passes.
// All shared exchanges bank-conflict-free; no registers live across barriers.
// The natural-order planes alias the sd buffer (free after pass-2 reads).
// ---------------------------------------------------------------------------
__global__ void __launch_bounds__(256) stft_kernel(const float* __restrict__ x,
                                                   float* __restrict__ out) {
    __shared__ c2 sd[4][576];        // p1->p2 skew 72; reused as nat planes
    __shared__ float exR[4][572];    // p2->p3 exchange, real plane
    __shared__ float exI[4][572];    // p2->p3 exchange, imag plane

    const int tid = threadIdx.x;
    const int u   = tid >> 6;        // FFT unit 0..3
    const int tau = tid & 63;
    const int t   = blockIdx.x * 4 + u;
    const int by  = blockIdx.y;
    const int b   = by >> 1;
    const int pr  = by & 1;          // channel pair (2pr, 2pr+1)
    const bool active = (t < TT);

    // nat planes alias sd[u] (1152 floats): natR at 0 (<=571), natI at 576
    float* natR = reinterpret_cast<float*>(sd[u]);
    float* natI = natR + 576;

    c2 v[8], o8[8];

    // ---- pass 1: windowed load, radix-8 over n2, twiddle W64^{n1*k0} ----
    if (active) {
        const float S = 0.70710678118654752f;
        const float c8[8] = {1.f,  S, 0.f, -S, -1.f, -S,  0.f,  S};
        const float s8[8] = {0.f,  S, 1.f,  S,  0.f, -S, -1.f, -S};
        float sth, cth;
        __sincosf((float)(2.0 * PI_D / 512.0) * (float)tau, &sth, &cth);

        const float* xa = x + (size_t)(b * CC + 2 * pr) * LSIG;
        const float* xb = xa + LSIG;
        const int p0 = t * HOP - 256;
        if (t >= 2 && t <= 1248) {           // interior: no reflection possible
#pragma unroll
            for (int n2 = 0; n2 < 8; n2++) {
                int s = p0 + n2 * 64 + tau;
                float cosn = c8[n2] * cth - s8[n2] * sth;    // cos(2*pi*n/512)
                float w = 0.5f - 0.5f * cosn;                // Hann
                v[n2].x = xa[s] * w;
                v[n2].y = xb[s] * w;
            }
        } else {
#pragma unroll
            for (int n2 = 0; n2 < 8; n2++) {
                int p = p0 + n2 * 64 + tau;
                int s = (p < 0) ? -p : ((p >= LSIG) ? 2 * LSIG - 2 - p : p);
                float cosn = c8[n2] * cth - s8[n2] * sth;
                float w = 0.5f - 0.5f * cosn;
                v[n2].x = xa[s] * w;
                v[n2].y = xb[s] * w;
            }
        }
        radix8(v, o8);
        int n1 = tau >> 3;
        float ss, cs;
        __sincosf((float)(-2.0 * PI_D / 64.0) * (float)n1, &ss, &cs);
        c2 step; step.x = cs; step.y = ss;                   // W64^{n1}
        c2 w; w.x = 1.f; w.y = 0.f;
#pragma unroll
        for (int k0 = 0; k0 < 8; k0++) {
            sd[u][k0 * SDS + tau] = cmul(o8[k0], w);         // * W64^{n1*k0}
            w = cmul(w, step);
        }
    }
    __syncthreads();

    // ---- pass 2: radix-8 over n1, twiddle, write exchange planes ----
    if (active) {
        const int k0 = tau >> 3;
        const int n0 = tau & 7;
#pragma unroll
        for (int n1 = 0; n1 < 8; n1++) v[n1] = sd[u][k0 * SDS + n1 * 8 + n0];
        radix8(v, o8);
        float s0, c0, ss, cs;
        __sincosf((float)(-2.0 * PI_D / 512.0) * (float)(n0 * k0), &s0, &c0);
        __sincosf((float)(-2.0 * PI_D / 64.0) * (float)n0, &ss, &cs);
        c2 w;    w.x = c0;   w.y = s0;                       // W512^{n0*k0}
        c2 step; step.x = cs; step.y = ss;                   // W64^{n0}
#pragma unroll
        for (int k1 = 0; k1 < 8; k1++) {
            c2 r = cmul(o8[k1], w);
            int e = EXI(k0, k1, n0);
            exR[u][e] = r.x;
            exI[u][e] = r.y;
            w = cmul(w, step);
        }
    }
    __syncthreads();   // pass-2 reads of sd complete -> sd reusable as nat

    // ---- pass 3: read exchange, radix-8 over n0, NSK planes into sd ----
    if (active) {
        const int k0 = tau >> 3;
        const int l  = tau & 7;      // = k1
#pragma unroll
        for (int n0 = 0; n0 < 8; n0++) {
            int e = EXI(k0, l, n0);
            v[n0].x = exR[u][e];
            v[n0].y = exI[u][e];
        }
        radix8(v, o8);               // o8[k2] = X[64*k2 + 8*l + k0]
#pragma unroll
        for (int k2 = 0; k2 < 8; k2++) {
            int a  = k2 * 64 + l * 8 + k0;
            int sa = NSK(a);
            natR[sa] = o8[k2].x;
            natI[sa] = o8[k2].y;
        }
    }
    __syncthreads();

    // ---- unpack 2 real spectra + write X groups + computed SV groups ----
    if (active) {
        float* row = out + ((size_t)b * TT + t) * KFEAT;
        const int ca = 2 * pr, cb = 2 * pr + 1;
        const float dta = g_dt[ca];
        const float dtb = g_dt[cb];
        float* aBase = row + ca * FDIM;
        float* bBase = row + cb * FDIM;
        for (int k = tau; k <= 256; k += 64) {
            int mk = (512 - k) & 511;
            int ska = NSK(k), skm = NSK(mk);
            c2 zk, zm;
            zk.x = natR[ska]; zk.y = natI[ska];
            zm.x = natR[skm]; zm.y = natI[skm];
            aBase[k]          = 0.5f * (zk.x + zm.x);   // A.re
            aBase[CF + k]     = 0.5f * (zk.y - zm.y);   // A.im
            bBase[k]          = 0.5f * (zk.y + zm.y);   // B.re
            bBase[CF + k]     = 0.5f * (zm.x - zk.x);   // B.im
            float sa, cA, sb, cB;
            __sincosf(SVCOEF * (float)k * dta, &sa, &cA);
            __sincosf(SVCOEF * (float)k * dtb, &sb, &cB);
            aBase[2 * CF + k] = 0.5f * cA;              // sv.re / ||sv||
            aBase[3 * CF + k] = 0.5f * sa;              // sv.im
            bBase[2 * CF + k] = 0.5f * cB;
            bBase[3 * CF + k] = 0.5f * sb;
        }
    }
}

// ---------------------------------------------------------------------------
extern "C" void kernel_launch(void* const* d_in, const int* in_sizes, int n_in,
                              void* d_out, int out_size) {
    const float* x     = (const float*)d_in[0];
    const float* angle = (const float*)d_in[1];
    const float* mic   = (const float*)d_in[2];
    float* out = (float*)d_out;

    prep_kernel<<<1, 64>>>(angle, mic);

    dim3 grid((TT + 3) / 4, BB * 2);
    stft_kernel<<<grid, 256>>>(x, out);
}